// round 6
// baseline (speedup 1.0000x reference)
#include <cuda_runtime.h>
#include <cuda_bf16.h>
#include <cstdint>

// ---------------------------------------------------------------------------
// Problem constants
// ---------------------------------------------------------------------------
#define BATCH  256
#define LIN    2048
#define HNODE  256
#define GLEN   24
#define LOUT   2025
#define TWOH   512
#define KDIM   96
#define NTLOC  8             // tiles of 128 l-positions per CTA (l-half)
#define NLOC   1056          // staged local positions (1024 + 23 + pad)
#define NQ     2096          // XiQ slots: 2*1048

// ---------------------------------------------------------------------------
// Shared memory layout (bytes)
// ---------------------------------------------------------------------------
#define OFF_XIQ  0                       // 2096 * 16 = 33536
#define OFF_TH   33536                   // 1056 * 8  = 8448
#define OFF_TL   41984                   // 8448 -> 50432
#define OFF_RED  33536                   // overlay (TH dead): 512 floats
#define SMEM_BYTES 50432

__device__ float g_pp[BATCH * 2 * TWOH];  // per (b, l-half): [max | unscaled sum]
__device__ float g_part[BATCH * 2];       // per (batch, o-half) head partials

// ---------------------------------------------------------------------------
// Helpers
// ---------------------------------------------------------------------------
static __device__ __forceinline__ void bsplit(float v, unsigned short& hi,
                                              unsigned short& lo) {
    __nv_bfloat16 h = __float2bfloat16(v);
    __nv_bfloat16 l = __float2bfloat16(v - __bfloat162float(h));
    hi = __bfloat16_as_ushort(h);
    lo = __bfloat16_as_ushort(l);
}

static __device__ __forceinline__ void mma_bf16(float* d, const uint32_t* a,
                                                uint32_t b0, uint32_t b1) {
    asm volatile(
        "mma.sync.aligned.m16n8k16.row.col.f32.bf16.bf16.f32 "
        "{%0,%1,%2,%3}, {%4,%5,%6,%7}, {%8,%9}, {%0,%1,%2,%3};"
        : "+f"(d[0]), "+f"(d[1]), "+f"(d[2]), "+f"(d[3])
        : "r"(a[0]), "r"(a[1]), "r"(a[2]), "r"(a[3]), "r"(b0), "r"(b1));
}

// ---------------------------------------------------------------------------
// Kernel 1: implicit-GEMM conv, 3-term bf16 split, packed 16B b-fragments.
// Grid: 1024 CTAs = (batch, h-half, l-half). 512 threads = 16 warps,
// warp grid 8(M) x 2(N); warp tile 16(h) x 64(l). 4 warps/SMSP for latency
// hiding; no main-loop barriers; nt-pair interleaved accumulator chains.
// ---------------------------------------------------------------------------
__global__ void __launch_bounds__(512, 1)
conv_mma_kernel(const float* __restrict__ x, const float* __restrict__ wConv,
                const float* __restrict__ wRect) {
    extern __shared__ char smem[];
    const int tid   = threadIdx.x;
    const int lane  = tid & 31;
    const int wid   = tid >> 5;
    const int b     = blockIdx.x >> 2;
    const int mh    = (blockIdx.x >> 1) & 1;
    const int lq    = blockIdx.x & 1;
    const int hbase = mh * 128;
    const int L0    = lq * 1024;
    const int wm    = wid & 7;         // warp M index (0..7), 16 rows each
    const int wn    = wid >> 3;        // warp N index (0..1)
    const int grp   = lane >> 2;       // 0..7
    const int tg    = lane & 3;        // 0..3
    const int kq    = tg * 2;

    unsigned long long* TH = (unsigned long long*)(smem + OFF_TH);
    unsigned long long* TL = (unsigned long long*)(smem + OFF_TL);

    // ---- phase 1: stage local x slice, interleaved bf16x4 hi/lo ----
    const float* xb = x + (size_t)b * 4 * LIN;
    for (int l = tid; l < NLOC; l += 512) {
        const int gl = L0 + l;
        unsigned long long hv = 0ull, lv = 0ull;
        if (gl < LIN) {
            unsigned short h0, l0, h1, l1, h2, l2, h3, l3;
            bsplit(xb[gl],           h0, l0);
            bsplit(xb[LIN + gl],     h1, l1);
            bsplit(xb[2 * LIN + gl], h2, l2);
            bsplit(xb[3 * LIN + gl], h3, l3);
            hv = (unsigned long long)h0 | ((unsigned long long)h1 << 16)
               | ((unsigned long long)h2 << 32) | ((unsigned long long)h3 << 48);
            lv = (unsigned long long)l0 | ((unsigned long long)l1 << 16)
               | ((unsigned long long)l2 << 32) | ((unsigned long long)l3 << 48);
        }
        TH[l] = hv;  TL[l] = lv;
    }
    __syncthreads();

    // ---- phase 2: build packed XiQ. slot(2l+p) = {b0h,b1h,b0l,b1l} ----
    {
        const uint32_t* THw = (const uint32_t*)TH;
        const uint32_t* TLw = (const uint32_t*)TL;
        uint4* XiQ = (uint4*)(smem + OFF_XIQ);
        for (int i = tid; i < NQ; i += 512) {
            uint4 q;
            q.x = THw[i];     q.y = THw[i + 4];
            q.z = TLw[i];     q.w = TLw[i + 4];
            XiQ[i] = q;
        }
    }

    // ---- A fragments straight from gmem (wConv is L2-resident) ----
    uint32_t aH[6][4], aL[6][4];
#pragma unroll
    for (int ks = 0; ks < 6; ++ks)
#pragma unroll
        for (int rr = 0; rr < 4; ++rr) {
            const int r  = wm * 16 + grp + (rr & 1) * 8;
            const int k0 = ks * 16 + kq + (rr >> 1) * 8;      // even
            const int base = (hbase + r) * KDIM + (k0 >> 2);
            const float f0 = wConv[base + (k0 & 3) * GLEN];
            const float f1 = wConv[base + ((k0 & 3) + 1) * GLEN];
            unsigned short h0, lo0, h1, lo1;
            bsplit(f0, h0, lo0);
            bsplit(f1, h1, lo1);
            aH[ks][rr] = (uint32_t)h0  | ((uint32_t)h1  << 16);
            aL[ks][rr] = (uint32_t)lo0 | ((uint32_t)lo1 << 16);
        }

    float rb[2];
    rb[0] = wRect[hbase + wm * 16 + grp];
    rb[1] = wRect[hbase + wm * 16 + 8 + grp];

    __syncthreads();

    const uint4* XiQ = (const uint4*)(smem + OFF_XIQ);
    // slot = 2*(t*128 + wn*64 + nt*8 + grp + 4ks + (tg>>1)) + (tg&1)
    const int sbase = 2 * (wn * 64 + grp + (tg >> 1)) + (tg & 1);

    float mx[2] = {0.f, 0.f};
    float sm[2] = {0.f, 0.f};
    const bool hasMask = (lq == 1);

    for (int t = 0; t < NTLOC; ++t) {
        const int base_t = sbase + 2 * t * 128;

        float d[8][4];
#pragma unroll
        for (int nt = 0; nt < 8; ++nt)
#pragma unroll
            for (int e = 0; e < 4; ++e) d[nt][e] = 0.f;

#pragma unroll
        for (int ks = 0; ks < 6; ++ks) {
#pragma unroll
            for (int ntp = 0; ntp < 4; ++ntp) {
                const int s0 = base_t + 2 * (ntp * 16 + 4 * ks);
                const uint4 q0 = XiQ[s0];
                const uint4 q1 = XiQ[s0 + 16];
                // interleaved: same-accumulator MMAs spaced by 2
                mma_bf16(d[2 * ntp],     aH[ks], q0.x, q0.y);
                mma_bf16(d[2 * ntp + 1], aH[ks], q1.x, q1.y);
                mma_bf16(d[2 * ntp],     aH[ks], q0.z, q0.w);
                mma_bf16(d[2 * ntp + 1], aH[ks], q1.z, q1.w);
                mma_bf16(d[2 * ntp],     aL[ks], q0.x, q0.y);
                mma_bf16(d[2 * ntp + 1], aL[ks], q1.x, q1.y);
            }
        }

        if (!(hasMask && t == NTLOC - 1)) {
#pragma unroll
            for (int nt = 0; nt < 8; ++nt)
#pragma unroll
                for (int e = 0; e < 4; ++e) {
                    const int rh = e >> 1;
                    float r = fmaxf(d[nt][e] + rb[rh], 0.f);
                    mx[rh] = fmaxf(mx[rh], r);
                    sm[rh] += r;
                }
        } else {
            const int lb = L0 + t * 128 + wn * 64;
#pragma unroll
            for (int nt = 0; nt < 8; ++nt)
#pragma unroll
                for (int e = 0; e < 4; ++e) {
                    const int rh = e >> 1;
                    const int n  = lb + nt * 8 + kq + (e & 1);
                    float r = fmaxf(d[nt][e] + rb[rh], 0.f);
                    if (n < LOUT) {
                        mx[rh] = fmaxf(mx[rh], r);
                        sm[rh] += r;
                    }
                }
        }
    }

    // ---- lane-group reduce, cross-wn combine, write partials ----
    __syncthreads();
    float* red = (float*)(smem + OFF_RED);    // 512 floats
#pragma unroll
    for (int rh = 0; rh < 2; ++rh) {
        float mv = mx[rh], sv = sm[rh];
        mv = fmaxf(mv, __shfl_xor_sync(0xffffffffu, mv, 1));
        sv +=        __shfl_xor_sync(0xffffffffu, sv, 1);
        mv = fmaxf(mv, __shfl_xor_sync(0xffffffffu, mv, 2));
        sv +=        __shfl_xor_sync(0xffffffffu, sv, 2);
        if (tg == 0) {
            const int m = wm * 16 + rh * 8 + grp;
            red[wn * 128 + m]       = mv;
            red[256 + wn * 128 + m] = sv;
        }
    }
    __syncthreads();

    if (tid < 128) {
        const float mv = fmaxf(red[tid], red[128 + tid]);
        const float sv = red[256 + tid] + red[384 + tid];
        float* pp = g_pp + (size_t)(b * 2 + lq) * TWOH;
        pp[hbase + tid]         = mv;
        pp[HNODE + hbase + tid] = sv;     // unscaled sum
    }
}

// ---------------------------------------------------------------------------
// Kernel 2: MLP head, batched GEMV with partial-pool combine in staging.
// Grid 128 = (64 batch-quads x 2 o-halves), 256 threads.
// ---------------------------------------------------------------------------
__global__ void __launch_bounds__(256)
mlp_kernel(const float* __restrict__ wH, const float* __restrict__ wHB,
           const float* __restrict__ wNeu) {
    __shared__ float4 prow[TWOH];
    __shared__ float  redsm[32];

    const int tid = threadIdx.x;
    const int bt  = blockIdx.x >> 1;
    const int oh  = blockIdx.x & 1;
    const int o   = oh * 256 + tid;
    const int b0  = bt * 4;

    for (int i = tid; i < TWOH; i += 256) {
        float4 v;
        const float inv = 1.0f / LOUT;
#pragma unroll
        for (int j = 0; j < 4; ++j) {
            const float* p0 = g_pp + (size_t)((b0 + j) * 2 + 0) * TWOH;
            const float* p1 = g_pp + (size_t)((b0 + j) * 2 + 1) * TWOH;
            float val = (i < HNODE) ? fmaxf(p0[i], p1[i])
                                    : (p0[i] + p1[i]) * inv;
            ((float*)&v)[j] = val;
        }
        prow[i] = v;
    }
    __syncthreads();

    float a0 = 0.f, a1 = 0.f, a2 = 0.f, a3 = 0.f;
#pragma unroll 8
    for (int i = 0; i < TWOH; ++i) {
        const float w = wH[i * TWOH + o];
        const float4 p = prow[i];
        a0 = fmaf(p.x, w, a0);
        a1 = fmaf(p.y, w, a1);
        a2 = fmaf(p.z, w, a2);
        a3 = fmaf(p.w, w, a3);
    }

    const float hb = wHB[o];
    const float wv = wNeu[o];
    float vals[4];
    vals[0] = fmaxf(a0 + hb, 0.f) * wv;
    vals[1] = fmaxf(a1 + hb, 0.f) * wv;
    vals[2] = fmaxf(a2 + hb, 0.f) * wv;
    vals[3] = fmaxf(a3 + hb, 0.f) * wv;

    const int lane = tid & 31, wid = tid >> 5;
#pragma unroll
    for (int j = 0; j < 4; ++j) {
        float v = vals[j];
        v += __shfl_xor_sync(0xffffffffu, v, 16);
        v += __shfl_xor_sync(0xffffffffu, v, 8);
        v += __shfl_xor_sync(0xffffffffu, v, 4);
        v += __shfl_xor_sync(0xffffffffu, v, 2);
        v += __shfl_xor_sync(0xffffffffu, v, 1);
        if (lane == 0) redsm[j * 8 + wid] = v;
    }
    __syncthreads();

    if (tid < 32) {
        float v = redsm[tid];
        v += __shfl_xor_sync(0xffffffffu, v, 4);
        v += __shfl_xor_sync(0xffffffffu, v, 2);
        v += __shfl_xor_sync(0xffffffffu, v, 1);
        if ((tid & 7) == 0)
            g_part[(b0 + (tid >> 3)) * 2 + oh] = v;
    }
}

// ---------------------------------------------------------------------------
// Kernel 3: out[b] = 0.5*(p0+p1) + wNeuBias
// ---------------------------------------------------------------------------
__global__ void __launch_bounds__(256)
final_kernel(const float* __restrict__ wNB, float* __restrict__ out) {
    const int b = threadIdx.x;
    out[b] = 0.5f * (g_part[2 * b] + g_part[2 * b + 1]) + wNB[0];
}

// ---------------------------------------------------------------------------
// Launch
// ---------------------------------------------------------------------------
extern "C" void kernel_launch(void* const* d_in, const int* in_sizes, int n_in,
                              void* d_out, int out_size) {
    const float* x     = (const float*)d_in[0];
    const float* wConv = (const float*)d_in[1];
    const float* wRect = (const float*)d_in[2];
    const float* wH    = (const float*)d_in[3];
    const float* wHB   = (const float*)d_in[4];
    const float* wNeu  = (const float*)d_in[5];
    const float* wNB   = (const float*)d_in[6];
    float* out = (float*)d_out;

    static int smem_set = 0;
    if (!smem_set) {
        cudaFuncSetAttribute(conv_mma_kernel,
                             cudaFuncAttributeMaxDynamicSharedMemorySize,
                             SMEM_BYTES);
        smem_set = 1;
    }

    conv_mma_kernel<<<BATCH * 4, 512, SMEM_BYTES>>>(x, wConv, wRect);
    mlp_kernel<<<128, 256>>>(wH, wHB, wNeu);
    final_kernel<<<1, 256>>>(wNB, out);
}